// round 2
// baseline (speedup 1.0000x reference)
#include <cuda_runtime.h>
#include <math.h>

#define TT 2048
#define DD 1024
#define HH 2048
#define EE 8
#define NA (2 * TT)   // total token-expert assignments (top-2)

// ---- scratch (static device globals; no allocation allowed) ----
__device__ int   g_cnt[EE];
__device__ int   g_off[EE];                    // exclusive prefix of g_cnt
__device__ int   g_tok[EE][TT];
__device__ float g_wt[EE][TT];
__device__ float g_h[(size_t)NA * HH];         // 33.5 MB compacted activations

__device__ __forceinline__ float gelu_tanh(float v) {
    const float c = 0.7978845608028654f;       // sqrt(2/pi)
    float u = c * (v + 0.044715f * v * v * v);
    return 0.5f * v * (1.0f + tanhf(u));
}

// ---------------- kernel 0: clear output + counters ----------------
__global__ void zero_kernel(float* out) {
    int i = blockIdx.x * blockDim.x + threadIdx.x;
    if (i < TT * DD) out[i] = 0.0f;
    if (i < EE) g_cnt[i] = 0;
}

// ---------------- kernel 1: gating ----------------
// one warp per token: logits[8] = x . Wg[:,e] + bg, top-2, softmax pair
__global__ void gate_kernel(const float* __restrict__ x,
                            const float* __restrict__ Wg,
                            const float* __restrict__ bg,
                            float* __restrict__ out, int write_tail) {
    int warp = (blockIdx.x * blockDim.x + threadIdx.x) >> 5;
    int lane = threadIdx.x & 31;
    if (warp >= TT) return;
    const float* xr = x + (size_t)warp * DD;

    float acc[EE];
#pragma unroll
    for (int e = 0; e < EE; e++) acc[e] = 0.0f;

    for (int i = lane; i < DD; i += 32) {
        float xv = xr[i];
        const float* wr = Wg + (size_t)i * EE;
#pragma unroll
        for (int e = 0; e < EE; e++) acc[e] += xv * wr[e];
    }
#pragma unroll
    for (int off = 16; off > 0; off >>= 1) {
#pragma unroll
        for (int e = 0; e < EE; e++)
            acc[e] += __shfl_down_sync(0xffffffffu, acc[e], off);
    }
    if (lane == 0) {
        float v[EE];
#pragma unroll
        for (int e = 0; e < EE; e++) v[e] = acc[e] + bg[e];
        // top-1 (strict >, ties -> lower index, matches lax.top_k)
        int i0 = 0; float v0 = v[0];
#pragma unroll
        for (int e = 1; e < EE; e++) if (v[e] > v0) { v0 = v[e]; i0 = e; }
        int i1 = -1; float v1 = -3.4e38f;
#pragma unroll
        for (int e = 0; e < EE; e++)
            if (e != i0 && v[e] > v1) { v1 = v[e]; i1 = e; }
        // softmax over (v0, v1), v0 >= v1
        float ex = __expf(v1 - v0);
        float inv = 1.0f / (1.0f + ex);
        float w0 = inv;
        float w1 = ex * inv;

        int p0 = atomicAdd(&g_cnt[i0], 1);
        g_tok[i0][p0] = warp; g_wt[i0][p0] = w0;
        int p1 = atomicAdd(&g_cnt[i1], 1);
        g_tok[i1][p1] = warp; g_wt[i1][p1] = w1;

        if (write_tail) {
            out[(size_t)TT * DD + warp * 2 + 0] = (float)i0;
            out[(size_t)TT * DD + warp * 2 + 1] = (float)i1;
        }
    }
}

// ---------------- kernel 1b: exclusive prefix over 8 counters ----------------
__global__ void scan_kernel() {
    if (threadIdx.x == 0) {
        int run = 0;
#pragma unroll
        for (int e = 0; e < EE; e++) { g_off[e] = run; run += g_cnt[e]; }
    }
}

// ---------------- grouped GEMM 1: h = gelu(Xg @ W1[e] + b1[e]) ----------------
// tiles: 64x64x16, 128 threads, 8x4 per thread
__global__ __launch_bounds__(128) void ffn1_kernel(const float* __restrict__ x,
                                                   const float* __restrict__ W1,
                                                   const float* __restrict__ b1) {
    const int e  = blockIdx.z;
    const int cnt = g_cnt[e];
    const int m0 = blockIdx.y * 64;
    if (m0 >= cnt) return;
    const int n0 = blockIdx.x * 64;
    const int off = g_off[e];

    __shared__ float As[16][68];
    __shared__ float Bs[16][68];

    const int tid = threadIdx.x;
    const int tn  = tid & 15;   // 16 threads over N (x4)
    const int tm  = tid >> 4;   // 8 threads over M (x8)

    const float* Bptr = W1 + (size_t)e * DD * HH;

    float accv[8][4];
#pragma unroll
    for (int i = 0; i < 8; i++)
#pragma unroll
        for (int j = 0; j < 4; j++) accv[i][j] = 0.0f;

    for (int k0 = 0; k0 < DD; k0 += 16) {
        // load A (gathered token rows), transposed into As[k][m]
#pragma unroll
        for (int l = 0; l < 2; l++) {
            int id = tid + l * 128;
            int m  = id >> 2;
            int kk = (id & 3) << 2;
            int r  = m0 + m;
            float4 v = make_float4(0.f, 0.f, 0.f, 0.f);
            if (r < cnt) {
                int t = g_tok[e][r];
                v = *(const float4*)(x + (size_t)t * DD + k0 + kk);
            }
            As[kk + 0][m] = v.x;
            As[kk + 1][m] = v.y;
            As[kk + 2][m] = v.z;
            As[kk + 3][m] = v.w;
        }
        // load B tile
#pragma unroll
        for (int l = 0; l < 2; l++) {
            int id = tid + l * 128;
            int k  = id >> 4;
            int nn = (id & 15) << 2;
            float4 v = *(const float4*)(Bptr + (size_t)(k0 + k) * HH + n0 + nn);
            *(float4*)&Bs[k][nn] = v;
        }
        __syncthreads();
#pragma unroll
        for (int k = 0; k < 16; k++) {
            float a[8], b[4];
            *(float4*)&a[0] = *(const float4*)&As[k][tm * 8];
            *(float4*)&a[4] = *(const float4*)&As[k][tm * 8 + 4];
            *(float4*)&b[0] = *(const float4*)&Bs[k][tn * 4];
#pragma unroll
            for (int i = 0; i < 8; i++)
#pragma unroll
                for (int j = 0; j < 4; j++) accv[i][j] += a[i] * b[j];
        }
        __syncthreads();
    }

    // epilogue: bias + gelu -> g_h (compacted rows)
    const float* brow = b1 + (size_t)e * HH + n0 + tn * 4;
    float bb[4];
    *(float4*)&bb[0] = *(const float4*)brow;
#pragma unroll
    for (int i = 0; i < 8; i++) {
        int r = m0 + tm * 8 + i;
        if (r >= cnt) continue;
        float4 hv;
        hv.x = gelu_tanh(accv[i][0] + bb[0]);
        hv.y = gelu_tanh(accv[i][1] + bb[1]);
        hv.z = gelu_tanh(accv[i][2] + bb[2]);
        hv.w = gelu_tanh(accv[i][3] + bb[3]);
        *(float4*)(g_h + ((size_t)(off + r)) * HH + n0 + tn * 4) = hv;
    }
}

// ---------------- grouped GEMM 2: out += w * (h @ W2[e] + b2[e]) ----------------
__global__ __launch_bounds__(128) void ffn2_kernel(const float* __restrict__ W2,
                                                   const float* __restrict__ b2,
                                                   float* __restrict__ out) {
    const int e  = blockIdx.z;
    const int cnt = g_cnt[e];
    const int m0 = blockIdx.y * 64;
    if (m0 >= cnt) return;
    const int n0 = blockIdx.x * 64;
    const int off = g_off[e];

    __shared__ float As[16][68];
    __shared__ float Bs[16][68];

    const int tid = threadIdx.x;
    const int tn  = tid & 15;
    const int tm  = tid >> 4;

    const float* Aptr = g_h + (size_t)off * HH;
    const float* Bptr = W2 + (size_t)e * HH * DD;

    float accv[8][4];
#pragma unroll
    for (int i = 0; i < 8; i++)
#pragma unroll
        for (int j = 0; j < 4; j++) accv[i][j] = 0.0f;

    for (int k0 = 0; k0 < HH; k0 += 16) {
#pragma unroll
        for (int l = 0; l < 2; l++) {
            int id = tid + l * 128;
            int m  = id >> 2;
            int kk = (id & 3) << 2;
            int r  = m0 + m;
            float4 v = make_float4(0.f, 0.f, 0.f, 0.f);
            if (r < cnt)
                v = *(const float4*)(Aptr + (size_t)r * HH + k0 + kk);
            As[kk + 0][m] = v.x;
            As[kk + 1][m] = v.y;
            As[kk + 2][m] = v.z;
            As[kk + 3][m] = v.w;
        }
#pragma unroll
        for (int l = 0; l < 2; l++) {
            int id = tid + l * 128;
            int k  = id >> 4;
            int nn = (id & 15) << 2;
            float4 v = *(const float4*)(Bptr + (size_t)(k0 + k) * DD + n0 + nn);
            *(float4*)&Bs[k][nn] = v;
        }
        __syncthreads();
#pragma unroll
        for (int k = 0; k < 16; k++) {
            float a[8], b[4];
            *(float4*)&a[0] = *(const float4*)&As[k][tm * 8];
            *(float4*)&a[4] = *(const float4*)&As[k][tm * 8 + 4];
            *(float4*)&b[0] = *(const float4*)&Bs[k][tn * 4];
#pragma unroll
            for (int i = 0; i < 8; i++)
#pragma unroll
                for (int j = 0; j < 4; j++) accv[i][j] += a[i] * b[j];
        }
        __syncthreads();
    }

    const float* brow = b2 + (size_t)e * DD + n0 + tn * 4;
    float bb[4];
    *(float4*)&bb[0] = *(const float4*)brow;
#pragma unroll
    for (int i = 0; i < 8; i++) {
        int r = m0 + tm * 8 + i;
        if (r >= cnt) continue;
        int   t = g_tok[e][r];
        float w = g_wt[e][r];
        float* orow = out + (size_t)t * DD + n0 + tn * 4;
#pragma unroll
        for (int j = 0; j < 4; j++)
            atomicAdd(&orow[j], w * (accv[i][j] + bb[j]));
    }
}

extern "C" void kernel_launch(void* const* d_in, const int* in_sizes, int n_in,
                              void* d_out, int out_size) {
    const float* x  = (const float*)d_in[0];   // [T, D]
    const float* Wg = (const float*)d_in[1];   // [D, E]
    const float* bg = (const float*)d_in[2];   // [E]
    const float* W1 = (const float*)d_in[3];   // [E, D, H]
    const float* b1 = (const float*)d_in[4];   // [E, H]
    const float* W2 = (const float*)d_in[5];   // [E, H, D]
    const float* b2 = (const float*)d_in[6];   // [E, D]
    float* out = (float*)d_out;

    int write_tail = (out_size >= TT * DD + 2 * TT) ? 1 : 0;

    zero_kernel<<<(TT * DD + 255) / 256, 256>>>(out);
    gate_kernel<<<TT / 8, 256>>>(x, Wg, bg, out, write_tail);
    scan_kernel<<<1, 32>>>();
    ffn1_kernel<<<dim3(HH / 64, TT / 64, EE), 128>>>(x, W1, b1);
    ffn2_kernel<<<dim3(DD / 64, TT / 64, EE), 128>>>(W2, b2, out);
}

// round 13
// speedup vs baseline: 1.1038x; 1.1038x over previous
#include <cuda_runtime.h>
#include <math.h>

#define TT 2048
#define DD 1024
#define HH 2048
#define EE 8
#define NA (2 * TT)

// ---- scratch (static device globals; no allocation allowed) ----
__device__ int   g_cnt[EE];
__device__ int   g_off[EE];
__device__ int   g_tok[EE][TT];
__device__ float g_wt[EE][TT];
__device__ float g_h[(size_t)NA * HH];   // 33.5 MB compacted activations

__device__ __forceinline__ float gelu_tanh(float v) {
    const float c = 0.7978845608028654f;       // sqrt(2/pi)
    float u = c * (v + 0.044715f * v * v * v);
    return 0.5f * v * (1.0f + tanhf(u));
}

// ---------------- kernel 0: clear output + counters ----------------
__global__ void zero_kernel(float* out) {
    int i = blockIdx.x * blockDim.x + threadIdx.x;
    if (i < TT * DD) out[i] = 0.0f;
    if (i < EE) g_cnt[i] = 0;
}

// ---------------- kernel 1: gating (one warp / token) ----------------
__global__ void gate_kernel(const float* __restrict__ x,
                            const float* __restrict__ Wg,
                            const float* __restrict__ bg,
                            float* __restrict__ out, int write_tail) {
    int warp = (blockIdx.x * blockDim.x + threadIdx.x) >> 5;
    int lane = threadIdx.x & 31;
    if (warp >= TT) return;
    const float* xr = x + (size_t)warp * DD;

    float acc[EE];
#pragma unroll
    for (int e = 0; e < EE; e++) acc[e] = 0.0f;
    for (int i = lane; i < DD; i += 32) {
        float xv = xr[i];
        const float* wr = Wg + (size_t)i * EE;
#pragma unroll
        for (int e = 0; e < EE; e++) acc[e] += xv * wr[e];
    }
#pragma unroll
    for (int off = 16; off > 0; off >>= 1)
#pragma unroll
        for (int e = 0; e < EE; e++)
            acc[e] += __shfl_down_sync(0xffffffffu, acc[e], off);
    if (lane == 0) {
        float v[EE];
#pragma unroll
        for (int e = 0; e < EE; e++) v[e] = acc[e] + bg[e];
        int i0 = 0; float v0 = v[0];
#pragma unroll
        for (int e = 1; e < EE; e++) if (v[e] > v0) { v0 = v[e]; i0 = e; }
        int i1 = -1; float v1 = -3.4e38f;
#pragma unroll
        for (int e = 0; e < EE; e++)
            if (e != i0 && v[e] > v1) { v1 = v[e]; i1 = e; }
        float ex = __expf(v1 - v0);
        float inv = 1.0f / (1.0f + ex);
        int p0 = atomicAdd(&g_cnt[i0], 1);
        g_tok[i0][p0] = warp; g_wt[i0][p0] = inv;
        int p1 = atomicAdd(&g_cnt[i1], 1);
        g_tok[i1][p1] = warp; g_wt[i1][p1] = ex * inv;
        if (write_tail) {
            out[(size_t)TT * DD + warp * 2 + 0] = (float)i0;
            out[(size_t)TT * DD + warp * 2 + 1] = (float)i1;
        }
    }
}

__global__ void scan_kernel() {
    if (threadIdx.x == 0) {
        int run = 0;
#pragma unroll
        for (int e = 0; e < EE; e++) { g_off[e] = run; run += g_cnt[e]; }
    }
}

// ---------------- SIMT grouped GEMM: CTA tile 128x128, K-chunk 16 ----------------
// 256 threads = 16(m) x 16(n), each thread 8x8 outputs.
// smem: As[16][132] (k-major, transposed), Bs[16][132]. 16.9 KB total, 2 CTAs/SM.

struct Tile { float As[16][132]; float Bs[16][132]; };

// prefetch one K=16 chunk: 2 A float4 + 2 B float4 per thread
template<bool GATHER>
__device__ __forceinline__ void fill_regs(
    float4 pa[2], float4 pb[2],
    const float* __restrict__ Abase, int lda, const int* __restrict__ toks,
    int m0, int cnt,
    const float* __restrict__ Bbase, int ldb, int n0, int k0) {
    int tid = threadIdx.x;
#pragma unroll
    for (int l = 0; l < 2; l++) {
        int id = tid + l * 256;          // 0..511
        int m  = id >> 2;                // 0..127
        int kk = (id & 3) << 2;          // 0,4,8,12
        int r  = m0 + m;
        if (r < cnt) {
            int row = GATHER ? toks[r] : r;
            pa[l] = *(const float4*)(Abase + (size_t)row * lda + k0 + kk);
        } else {
            pa[l] = make_float4(0.f, 0.f, 0.f, 0.f);
        }
        int k  = id >> 5;                // 0..15
        int nn = (id & 31) << 2;         // 0..124
        pb[l] = *(const float4*)(Bbase + (size_t)(k0 + k) * ldb + n0 + nn);
    }
}

__device__ __forceinline__ void store_regs(Tile* tl, const float4 pa[2], const float4 pb[2]) {
    int tid = threadIdx.x;
#pragma unroll
    for (int l = 0; l < 2; l++) {
        int id = tid + l * 256;
        int m  = id >> 2;
        int kk = (id & 3) << 2;
        tl->As[kk + 0][m] = pa[l].x;
        tl->As[kk + 1][m] = pa[l].y;
        tl->As[kk + 2][m] = pa[l].z;
        tl->As[kk + 3][m] = pa[l].w;
        int k  = id >> 5;
        int nn = (id & 31) << 2;
        *(float4*)&tl->Bs[k][nn] = pb[l];
    }
}

__device__ __forceinline__ void compute_chunk(const Tile* tl, int tm, int tn,
                                              float acc[8][8]) {
#pragma unroll
    for (int k = 0; k < 16; k++) {
        float a[8], b[8];
        *(float4*)&a[0] = *(const float4*)&tl->As[k][tm * 8];
        *(float4*)&a[4] = *(const float4*)&tl->As[k][tm * 8 + 4];
        *(float4*)&b[0] = *(const float4*)&tl->Bs[k][tn * 8];
        *(float4*)&b[4] = *(const float4*)&tl->Bs[k][tn * 8 + 4];
#pragma unroll
        for (int i = 0; i < 8; i++)
#pragma unroll
            for (int j = 0; j < 8; j++) acc[i][j] += a[i] * b[j];
    }
}

template<bool GATHER>
__device__ __forceinline__ void simt_gemm(
    Tile* tl,
    const float* __restrict__ Abase, int lda, const int* __restrict__ toks,
    int m0, int cnt,
    const float* __restrict__ Bbase, int ldb, int n0, int K,
    float acc[8][8]) {
    const int tid = threadIdx.x;
    const int tn = tid & 15, tm = tid >> 4;
#pragma unroll
    for (int i = 0; i < 8; i++)
#pragma unroll
        for (int j = 0; j < 8; j++) acc[i][j] = 0.0f;

    const int nchunks = K >> 4;
    float4 pa[2], pb[2];
    fill_regs<GATHER>(pa, pb, Abase, lda, toks, m0, cnt, Bbase, ldb, n0, 0);
    for (int ch = 0; ch < nchunks; ch++) {
        __syncthreads();                  // prior compute done before overwrite
        store_regs(tl, pa, pb);
        __syncthreads();                  // tile visible
        if (ch + 1 < nchunks)             // overlap next global loads with compute
            fill_regs<GATHER>(pa, pb, Abase, lda, toks, m0, cnt, Bbase, ldb, n0,
                              (ch + 1) << 4);
        compute_chunk(tl, tm, tn, acc);
    }
}

// ---------------- ffn1: h = gelu(Xg @ W1[e] + b1[e]) ----------------
__global__ __launch_bounds__(256, 2) void ffn1_kernel(const float* __restrict__ x,
                                                      const float* __restrict__ W1,
                                                      const float* __restrict__ b1) {
    __shared__ Tile tl;
    const int e   = blockIdx.z;
    const int cnt = g_cnt[e];
    const int m0  = blockIdx.y * 128;
    if (m0 >= cnt) return;
    const int n0  = blockIdx.x * 128;
    const int off = g_off[e];

    float acc[8][8];
    simt_gemm<true>(&tl, x, DD, g_tok[e], m0, cnt,
                    W1 + (size_t)e * DD * HH, HH, n0, DD, acc);

    const int tn = threadIdx.x & 15, tm = threadIdx.x >> 4;
    const float* bias = b1 + (size_t)e * HH + n0 + tn * 8;
    float bb[8];
    *(float4*)&bb[0] = *(const float4*)bias;
    *(float4*)&bb[4] = *(const float4*)(bias + 4);
#pragma unroll
    for (int i = 0; i < 8; i++) {
        int r = m0 + tm * 8 + i;
        if (r >= cnt) continue;
        float* hrow = g_h + (size_t)(off + r) * HH + n0 + tn * 8;
        float4 v0, v1;
        v0.x = gelu_tanh(acc[i][0] + bb[0]);
        v0.y = gelu_tanh(acc[i][1] + bb[1]);
        v0.z = gelu_tanh(acc[i][2] + bb[2]);
        v0.w = gelu_tanh(acc[i][3] + bb[3]);
        v1.x = gelu_tanh(acc[i][4] + bb[4]);
        v1.y = gelu_tanh(acc[i][5] + bb[5]);
        v1.z = gelu_tanh(acc[i][6] + bb[6]);
        v1.w = gelu_tanh(acc[i][7] + bb[7]);
        *(float4*)(hrow)     = v0;
        *(float4*)(hrow + 4) = v1;
    }
}

// ---------------- ffn2: out += w * (h @ W2[e] + b2[e]) ----------------
__global__ __launch_bounds__(256, 2) void ffn2_kernel(const float* __restrict__ W2,
                                                      const float* __restrict__ b2,
                                                      float* __restrict__ out) {
    __shared__ Tile tl;
    const int e   = blockIdx.z;
    const int cnt = g_cnt[e];
    const int m0  = blockIdx.y * 128;
    if (m0 >= cnt) return;
    const int n0  = blockIdx.x * 128;
    const int off = g_off[e];

    float acc[8][8];
    simt_gemm<false>(&tl, g_h + (size_t)off * HH, HH, (const int*)0, m0, cnt,
                     W2 + (size_t)e * HH * DD, DD, n0, HH, acc);

    const int tn = threadIdx.x & 15, tm = threadIdx.x >> 4;
    const float* bias = b2 + (size_t)e * DD + n0 + tn * 8;
    float bb[8];
    *(float4*)&bb[0] = *(const float4*)bias;
    *(float4*)&bb[4] = *(const float4*)(bias + 4);
#pragma unroll
    for (int i = 0; i < 8; i++) {
        int r = m0 + tm * 8 + i;
        if (r >= cnt) continue;
        int   t = g_tok[e][r];
        float w = g_wt[e][r];
        float* orow = out + (size_t)t * DD + n0 + tn * 8;
#pragma unroll
        for (int j = 0; j < 8; j++)
            atomicAdd(&orow[j], w * (acc[i][j] + bb[j]));
    }
}

// ---------------- launch ----------------
extern "C" void kernel_launch(void* const* d_in, const int* in_sizes, int n_in,
                              void* d_out, int out_size) {
    const float* x  = (const float*)d_in[0];   // [T, D]
    const float* Wg = (const float*)d_in[1];   // [D, E]
    const float* bg = (const float*)d_in[2];   // [E]
    const float* W1 = (const float*)d_in[3];   // [E, D, H]
    const float* b1 = (const float*)d_in[4];   // [E, H]
    const float* W2 = (const float*)d_in[5];   // [E, H, D]
    const float* b2 = (const float*)d_in[6];   // [E, D]
    float* out = (float*)d_out;

    int write_tail = (out_size >= TT * DD + 2 * TT) ? 1 : 0;

    zero_kernel<<<(TT * DD + 255) / 256, 256>>>(out);
    gate_kernel<<<TT / 8, 256>>>(x, Wg, bg, out, write_tail);
    scan_kernel<<<1, 32>>>();
    ffn1_kernel<<<dim3(HH / 128, TT / 128, EE), 256>>>(x, W1, b1);
    ffn2_kernel<<<dim3(DD / 128, TT / 128, EE), 256>>>(W2, b2, out);
}

// round 14
// speedup vs baseline: 1.9993x; 1.8112x over previous
#include <cuda_runtime.h>
#include <cuda_bf16.h>
#include <math.h>
#include <stdint.h>

#define TT 2048
#define DD 1024
#define HH 2048
#define EE 8
#define NA (2 * TT)

// ---- scratch (static device globals; no allocation allowed) ----
__device__ int   g_cnt[EE];
__device__ int   g_off[EE];
__device__ int   g_tok[EE][TT];
__device__ float g_wt[EE][TT];
__device__ float g_h[(size_t)NA * HH];   // 33.5 MB fp32 activations (R13-proven)

__device__ __forceinline__ float gelu_tanh(float v) {
    const float c = 0.7978845608028654f;
    float u = c * (v + 0.044715f * v * v * v);
    return 0.5f * v * (1.0f + tanhf(u));
}
__device__ __forceinline__ void split_bf16(float v, __nv_bfloat16& h, __nv_bfloat16& l) {
    h = __float2bfloat16_rn(v);
    l = __float2bfloat16_rn(v - __bfloat162float(h));
}
__device__ __forceinline__ void mma16816(float* c, const uint32_t* a, const uint32_t* b) {
    asm volatile("mma.sync.aligned.m16n8k16.row.col.f32.bf16.bf16.f32 "
                 "{%0,%1,%2,%3}, {%4,%5,%6,%7}, {%8,%9}, {%0,%1,%2,%3};"
                 : "+f"(c[0]), "+f"(c[1]), "+f"(c[2]), "+f"(c[3])
                 : "r"(a[0]), "r"(a[1]), "r"(a[2]), "r"(a[3]), "r"(b[0]), "r"(b[1]));
}

// ---------------- kernel 0: clear output + counters ----------------
__global__ void zero_kernel(float* out) {
    int i = blockIdx.x * blockDim.x + threadIdx.x;
    if (i < TT * DD) out[i] = 0.0f;
    if (i < EE) g_cnt[i] = 0;
}

// ---------------- kernel 1: gating (one warp / token) ----------------
__global__ void gate_kernel(const float* __restrict__ x,
                            const float* __restrict__ Wg,
                            const float* __restrict__ bg,
                            float* __restrict__ out, int write_tail) {
    int warp = (blockIdx.x * blockDim.x + threadIdx.x) >> 5;
    int lane = threadIdx.x & 31;
    if (warp >= TT) return;
    const float* xr = x + (size_t)warp * DD;
    float acc[EE];
#pragma unroll
    for (int e = 0; e < EE; e++) acc[e] = 0.0f;
    for (int i = lane; i < DD; i += 32) {
        float xv = xr[i];
        const float* wr = Wg + (size_t)i * EE;
#pragma unroll
        for (int e = 0; e < EE; e++) acc[e] += xv * wr[e];
    }
#pragma unroll
    for (int off = 16; off > 0; off >>= 1)
#pragma unroll
        for (int e = 0; e < EE; e++)
            acc[e] += __shfl_down_sync(0xffffffffu, acc[e], off);
    if (lane == 0) {
        float v[EE];
#pragma unroll
        for (int e = 0; e < EE; e++) v[e] = acc[e] + bg[e];
        int i0 = 0; float v0 = v[0];
#pragma unroll
        for (int e = 1; e < EE; e++) if (v[e] > v0) { v0 = v[e]; i0 = e; }
        int i1 = -1; float v1 = -3.4e38f;
#pragma unroll
        for (int e = 0; e < EE; e++)
            if (e != i0 && v[e] > v1) { v1 = v[e]; i1 = e; }
        float ex = __expf(v1 - v0);
        float inv = 1.0f / (1.0f + ex);
        int p0 = atomicAdd(&g_cnt[i0], 1);
        g_tok[i0][p0] = warp; g_wt[i0][p0] = inv;
        int p1 = atomicAdd(&g_cnt[i1], 1);
        g_tok[i1][p1] = warp; g_wt[i1][p1] = ex * inv;
        if (write_tail) {
            out[(size_t)TT * DD + warp * 2 + 0] = (float)i0;
            out[(size_t)TT * DD + warp * 2 + 1] = (float)i1;
        }
    }
}

__global__ void scan_kernel() {
    if (threadIdx.x == 0) {
        int run = 0;
#pragma unroll
        for (int e = 0; e < EE; e++) { g_off[e] = run; run += g_cnt[e]; }
    }
}

// ---------------- HMMA grouped GEMM with in-kernel bf16 split ----------------
// CTA 128x128, 256 threads, warps 2(m) x 4(n), warp tile 64x32, K-chunk 16.
// SMEM planes (bf16): Ah, Al (A [m][k]), Bh, Bl (B transposed to [n][k]).
// Row stride 36 B (16 bf16 + 2 pad). Plane 128*36 = 4608 B; total 18432 B static.
#define PAD   36
#define PLANE 4608
#define SMEMB (4 * PLANE)

// prefetch one fp32 K=16 chunk: A 2x float4; B 8 strided floats (lane-interleaved n)
template<bool GATHER>
__device__ __forceinline__ void fill_regs(
    float4 pa[2], float pbv[2][4],
    const float* __restrict__ Abase, int lda, const int* __restrict__ toks,
    int m0, int cnt,
    const float* __restrict__ Bbase, int ldb, int n0, int k0) {
    int tid = threadIdx.x;
#pragma unroll
    for (int l = 0; l < 2; l++) {
        int id = tid + l * 256;
        int m  = id >> 2;
        int kk = (id & 3) << 2;
        int r  = m0 + m;
        if (r < cnt) {
            int row = GATHER ? toks[r] : r;
            pa[l] = *(const float4*)(Abase + (size_t)row * lda + k0 + kk);
        } else {
            pa[l] = make_float4(0.f, 0.f, 0.f, 0.f);
        }
        int k = (tid >> 5) + 8 * l;
        const float* bp = Bbase + (size_t)(k0 + k) * ldb + n0 + (tid & 31);
#pragma unroll
        for (int i = 0; i < 4; i++) pbv[l][i] = bp[32 * i];
    }
}

// convert + store: A -> [m][k] planes, B -> transposed [n][k] planes
__device__ __forceinline__ void store_stage(char* smem, const float4 pa[2],
                                            const float pbv[2][4]) {
    int tid = threadIdx.x;
#pragma unroll
    for (int l = 0; l < 2; l++) {
        int id = tid + l * 256;
        int m  = id >> 2;
        int kk = (id & 3) << 2;
        float av[4] = {pa[l].x, pa[l].y, pa[l].z, pa[l].w};
        __nv_bfloat16 hi[4], lo[4];
#pragma unroll
        for (int j = 0; j < 4; j++) split_bf16(av[j], hi[j], lo[j]);
        char* ph = smem + m * PAD + kk * 2;
        *(__nv_bfloat162*)(ph)     = __nv_bfloat162(hi[0], hi[1]);
        *(__nv_bfloat162*)(ph + 4) = __nv_bfloat162(hi[2], hi[3]);
        char* pl = ph + PLANE;
        *(__nv_bfloat162*)(pl)     = __nv_bfloat162(lo[0], lo[1]);
        *(__nv_bfloat162*)(pl + 4) = __nv_bfloat162(lo[2], lo[3]);

        int k = (tid >> 5) + 8 * l;
#pragma unroll
        for (int i = 0; i < 4; i++) {
            int n = (tid & 31) + 32 * i;
            __nv_bfloat16 bh, bl;
            split_bf16(pbv[l][i], bh, bl);
            *(__nv_bfloat16*)(smem + 2 * PLANE + n * PAD + k * 2) = bh;
            *(__nv_bfloat16*)(smem + 3 * PLANE + n * PAD + k * 2) = bl;
        }
    }
}

// fragment loads at PTX mma.m16n8k16 coordinates + 3-product split mma
__device__ __forceinline__ void compute_stage(const char* smem, int warp_m, int warp_n,
                                              int lane, float acc[4][4][4]) {
    const int g = lane >> 2;
    const int c = lane & 3;
    uint32_t bh[4][2], bl[4][2];
#pragma unroll
    for (int nt = 0; nt < 4; nt++) {
        const char* p = smem + 2 * PLANE + (uint32_t)(warp_n * 32 + nt * 8 + g) * PAD + c * 4;
        bh[nt][0] = *(const uint32_t*)(p);
        bh[nt][1] = *(const uint32_t*)(p + 16);
        const char* q = p + PLANE;
        bl[nt][0] = *(const uint32_t*)(q);
        bl[nt][1] = *(const uint32_t*)(q + 16);
    }
#pragma unroll
    for (int mt = 0; mt < 4; mt++) {
        const char* p = smem + (uint32_t)(warp_m * 64 + mt * 16 + g) * PAD + c * 4;
        uint32_t ah[4], al[4];
        ah[0] = *(const uint32_t*)(p);
        ah[1] = *(const uint32_t*)(p + 8 * PAD);
        ah[2] = *(const uint32_t*)(p + 16);
        ah[3] = *(const uint32_t*)(p + 8 * PAD + 16);
        const char* q = p + PLANE;
        al[0] = *(const uint32_t*)(q);
        al[1] = *(const uint32_t*)(q + 8 * PAD);
        al[2] = *(const uint32_t*)(q + 16);
        al[3] = *(const uint32_t*)(q + 8 * PAD + 16);
#pragma unroll
        for (int nt = 0; nt < 4; nt++) {
            mma16816(acc[mt][nt], ah, bh[nt]);
            mma16816(acc[mt][nt], ah, bl[nt]);
            mma16816(acc[mt][nt], al, bh[nt]);
        }
    }
}

template<bool GATHER>
__device__ __forceinline__ void mma_gemm(
    char* smem,
    const float* __restrict__ Abase, int lda, const int* __restrict__ toks,
    int m0, int cnt,
    const float* __restrict__ Bbase, int ldb, int n0, int K,
    float acc[4][4][4]) {
    const int lane = threadIdx.x & 31;
    const int wid  = threadIdx.x >> 5;
    const int warp_m = wid & 1, warp_n = wid >> 1;
#pragma unroll
    for (int i = 0; i < 4; i++)
#pragma unroll
        for (int j = 0; j < 4; j++)
#pragma unroll
            for (int q = 0; q < 4; q++) acc[i][j][q] = 0.0f;

    const int nchunks = K >> 4;
    float4 pa[2];
    float  pbv[2][4];
    fill_regs<GATHER>(pa, pbv, Abase, lda, toks, m0, cnt, Bbase, ldb, n0, 0);
    for (int ch = 0; ch < nchunks; ch++) {
        __syncthreads();               // prior compute done before overwrite
        store_stage(smem, pa, pbv);
        __syncthreads();               // tile visible
        if (ch + 1 < nchunks)          // overlap next global loads with compute
            fill_regs<GATHER>(pa, pbv, Abase, lda, toks, m0, cnt, Bbase, ldb, n0,
                              (ch + 1) << 4);
        compute_stage(smem, warp_m, warp_n, lane, acc);
    }
}

// ---------------- ffn1: h = gelu(Xg @ W1[e] + b1[e]) ----------------
__global__ __launch_bounds__(256, 2) void ffn1_kernel(const float* __restrict__ x,
                                                      const float* __restrict__ W1,
                                                      const float* __restrict__ b1) {
    __shared__ __align__(16) char smem[SMEMB];
    const int e   = blockIdx.z;
    const int cnt = g_cnt[e];
    const int m0  = blockIdx.y * 128;
    if (m0 >= cnt) return;
    const int n0  = blockIdx.x * 128;
    const int off = g_off[e];

    float acc[4][4][4];
    mma_gemm<true>(smem, x, DD, g_tok[e], m0, cnt,
                   W1 + (size_t)e * DD * HH, HH, n0, DD, acc);

    const int lane = threadIdx.x & 31;
    const int wid  = threadIdx.x >> 5;
    const int warp_m = wid & 1, warp_n = wid >> 1;
    const int g = lane >> 2, c2 = (lane & 3) << 1;
    const float* bias = b1 + (size_t)e * HH;
#pragma unroll
    for (int mt = 0; mt < 4; mt++) {
        int rl = m0 + warp_m * 64 + mt * 16 + g;
        int rh = rl + 8;
#pragma unroll
        for (int nt = 0; nt < 4; nt++) {
            int n = n0 + warp_n * 32 + nt * 8 + c2;
            float bn0 = bias[n], bn1 = bias[n + 1];
            if (rl < cnt) {
                float2 v;
                v.x = gelu_tanh(acc[mt][nt][0] + bn0);
                v.y = gelu_tanh(acc[mt][nt][1] + bn1);
                *(float2*)(g_h + (size_t)(off + rl) * HH + n) = v;
            }
            if (rh < cnt) {
                float2 v;
                v.x = gelu_tanh(acc[mt][nt][2] + bn0);
                v.y = gelu_tanh(acc[mt][nt][3] + bn1);
                *(float2*)(g_h + (size_t)(off + rh) * HH + n) = v;
            }
        }
    }
}

// ---------------- ffn2: out += w * (h @ W2[e] + b2[e]) ----------------
__global__ __launch_bounds__(256, 2) void ffn2_kernel(const float* __restrict__ W2,
                                                      const float* __restrict__ b2,
                                                      float* __restrict__ out) {
    __shared__ __align__(16) char smem[SMEMB];
    const int e   = blockIdx.z;
    const int cnt = g_cnt[e];
    const int m0  = blockIdx.y * 128;
    if (m0 >= cnt) return;
    const int n0  = blockIdx.x * 128;
    const int off = g_off[e];

    float acc[4][4][4];
    mma_gemm<false>(smem, g_h + (size_t)off * HH, HH, (const int*)0, m0, cnt,
                    W2 + (size_t)e * HH * DD, DD, n0, HH, acc);

    const int lane = threadIdx.x & 31;
    const int wid  = threadIdx.x >> 5;
    const int warp_m = wid & 1, warp_n = wid >> 1;
    const int g = lane >> 2, c2 = (lane & 3) << 1;
    const float* bias = b2 + (size_t)e * DD;
#pragma unroll
    for (int mt = 0; mt < 4; mt++) {
        int rl = m0 + warp_m * 64 + mt * 16 + g;
        int rh = rl + 8;
        int tl = 0, th = 0; float wl = 0.0f, wh = 0.0f;
        if (rl < cnt) { tl = g_tok[e][rl]; wl = g_wt[e][rl]; }
        if (rh < cnt) { th = g_tok[e][rh]; wh = g_wt[e][rh]; }
#pragma unroll
        for (int nt = 0; nt < 4; nt++) {
            int n = n0 + warp_n * 32 + nt * 8 + c2;
            float bn0 = bias[n], bn1 = bias[n + 1];
            if (rl < cnt) {
                float* o = out + (size_t)tl * DD + n;
                atomicAdd(&o[0], wl * (acc[mt][nt][0] + bn0));
                atomicAdd(&o[1], wl * (acc[mt][nt][1] + bn1));
            }
            if (rh < cnt) {
                float* o = out + (size_t)th * DD + n;
                atomicAdd(&o[0], wh * (acc[mt][nt][2] + bn0));
                atomicAdd(&o[1], wh * (acc[mt][nt][3] + bn1));
            }
        }
    }
}

// ---------------- launch ----------------
extern "C" void kernel_launch(void* const* d_in, const int* in_sizes, int n_in,
                              void* d_out, int out_size) {
    const float* x  = (const float*)d_in[0];   // [T, D]
    const float* Wg = (const float*)d_in[1];   // [D, E]
    const float* bg = (const float*)d_in[2];   // [E]
    const float* W1 = (const float*)d_in[3];   // [E, D, H]
    const float* b1 = (const float*)d_in[4];   // [E, H]
    const float* W2 = (const float*)d_in[5];   // [E, H, D]
    const float* b2 = (const float*)d_in[6];   // [E, D]
    float* out = (float*)d_out;

    int write_tail = (out_size >= TT * DD + 2 * TT) ? 1 : 0;

    zero_kernel<<<(TT * DD + 255) / 256, 256>>>(out);
    gate_kernel<<<TT / 8, 256>>>(x, Wg, bg, out, write_tail);
    scan_kernel<<<1, 32>>>();
    ffn1_kernel<<<dim3(HH / 128, TT / 128, EE), 256>>>(x, W1, b1);
    ffn2_kernel<<<dim3(DD / 128, TT / 128, EE), 256>>>(W2, b2, out);
}

// round 15
// speedup vs baseline: 2.0064x; 1.0036x over previous
#include <cuda_runtime.h>
#include <cuda_bf16.h>
#include <math.h>
#include <stdint.h>

#define TT 2048
#define DD 1024
#define HH 2048
#define EE 8
#define NA (2 * TT)

// ---- scratch (static device globals; no allocation allowed) ----
__device__ int   g_cnt[EE];
__device__ int   g_off[EE];
__device__ int   g_tok[EE][TT];
__device__ float g_wt[EE][TT];
__device__ float g_h[(size_t)NA * HH];   // 33.5 MB fp32 activations

__device__ __forceinline__ float gelu_tanh(float v) {
    const float c = 0.7978845608028654f;
    float u = c * (v + 0.044715f * v * v * v);
    return 0.5f * v * (1.0f + tanhf(u));
}
__device__ __forceinline__ void split_bf16(float v, __nv_bfloat16& h, __nv_bfloat16& l) {
    h = __float2bfloat16_rn(v);
    l = __float2bfloat16_rn(v - __bfloat162float(h));
}
__device__ __forceinline__ void mma16816(float* c, const uint32_t* a, const uint32_t* b) {
    asm volatile("mma.sync.aligned.m16n8k16.row.col.f32.bf16.bf16.f32 "
                 "{%0,%1,%2,%3}, {%4,%5,%6,%7}, {%8,%9}, {%0,%1,%2,%3};"
                 : "+f"(c[0]), "+f"(c[1]), "+f"(c[2]), "+f"(c[3])
                 : "r"(a[0]), "r"(a[1]), "r"(a[2]), "r"(a[3]), "r"(b[0]), "r"(b[1]));
}

// ---------------- kernel 0: clear output + counters ----------------
__global__ void zero_kernel(float* out) {
    int i = blockIdx.x * blockDim.x + threadIdx.x;
    if (i < TT * DD) out[i] = 0.0f;
    if (i < EE) g_cnt[i] = 0;
}

// ---------------- kernel 1: gating (one warp / token) ----------------
__global__ void gate_kernel(const float* __restrict__ x,
                            const float* __restrict__ Wg,
                            const float* __restrict__ bg,
                            float* __restrict__ out, int write_tail) {
    int warp = (blockIdx.x * blockDim.x + threadIdx.x) >> 5;
    int lane = threadIdx.x & 31;
    if (warp >= TT) return;
    const float* xr = x + (size_t)warp * DD;
    float acc[EE];
#pragma unroll
    for (int e = 0; e < EE; e++) acc[e] = 0.0f;
    for (int i = lane; i < DD; i += 32) {
        float xv = xr[i];
        const float* wr = Wg + (size_t)i * EE;
#pragma unroll
        for (int e = 0; e < EE; e++) acc[e] += xv * wr[e];
    }
#pragma unroll
    for (int off = 16; off > 0; off >>= 1)
#pragma unroll
        for (int e = 0; e < EE; e++)
            acc[e] += __shfl_down_sync(0xffffffffu, acc[e], off);
    if (lane == 0) {
        float v[EE];
#pragma unroll
        for (int e = 0; e < EE; e++) v[e] = acc[e] + bg[e];
        int i0 = 0; float v0 = v[0];
#pragma unroll
        for (int e = 1; e < EE; e++) if (v[e] > v0) { v0 = v[e]; i0 = e; }
        int i1 = -1; float v1 = -3.4e38f;
#pragma unroll
        for (int e = 0; e < EE; e++)
            if (e != i0 && v[e] > v1) { v1 = v[e]; i1 = e; }
        float ex = __expf(v1 - v0);
        float inv = 1.0f / (1.0f + ex);
        int p0 = atomicAdd(&g_cnt[i0], 1);
        g_tok[i0][p0] = warp; g_wt[i0][p0] = inv;
        int p1 = atomicAdd(&g_cnt[i1], 1);
        g_tok[i1][p1] = warp; g_wt[i1][p1] = ex * inv;
        if (write_tail) {
            out[(size_t)TT * DD + warp * 2 + 0] = (float)i0;
            out[(size_t)TT * DD + warp * 2 + 1] = (float)i1;
        }
    }
}

__global__ void scan_kernel() {
    if (threadIdx.x == 0) {
        int run = 0;
#pragma unroll
        for (int e = 0; e < EE; e++) { g_off[e] = run; run += g_cnt[e]; }
    }
}

// ---------------- HMMA grouped GEMM with in-kernel bf16 split ----------------
// CTA 128x128, 256 threads, warps 2(m) x 4(n), warp tile 64x32, K-chunk 16.
// SMEM planes (bf16): Ah, Al (A [m][k]), Bh, Bl (B transposed to [n][k]).
// Row stride 36 B. Plane 4608 B; stage 18432 B; DOUBLE buffered = 36864 B static.
#define PAD    36
#define PLANE  4608
#define STAGEB 18432
#define SMEMB  (2 * STAGEB)

// prefetch one fp32 K=16 chunk: A 2x float4; B 8 strided floats (lane-interleaved n)
template<bool GATHER>
__device__ __forceinline__ void fill_regs(
    float4 pa[2], float pbv[2][4],
    const float* __restrict__ Abase, int lda, const int* __restrict__ toks,
    int m0, int cnt,
    const float* __restrict__ Bbase, int ldb, int n0, int k0) {
    int tid = threadIdx.x;
#pragma unroll
    for (int l = 0; l < 2; l++) {
        int id = tid + l * 256;
        int m  = id >> 2;
        int kk = (id & 3) << 2;
        int r  = m0 + m;
        if (r < cnt) {
            int row = GATHER ? toks[r] : r;
            pa[l] = *(const float4*)(Abase + (size_t)row * lda + k0 + kk);
        } else {
            pa[l] = make_float4(0.f, 0.f, 0.f, 0.f);
        }
        int k = (tid >> 5) + 8 * l;
        const float* bp = Bbase + (size_t)(k0 + k) * ldb + n0 + (tid & 31);
#pragma unroll
        for (int i = 0; i < 4; i++) pbv[l][i] = bp[32 * i];
    }
}

// convert + store: A -> [m][k] planes, B -> transposed [n][k] planes
__device__ __forceinline__ void store_stage(char* smem, const float4 pa[2],
                                            const float pbv[2][4]) {
    int tid = threadIdx.x;
#pragma unroll
    for (int l = 0; l < 2; l++) {
        int id = tid + l * 256;
        int m  = id >> 2;
        int kk = (id & 3) << 2;
        float av[4] = {pa[l].x, pa[l].y, pa[l].z, pa[l].w};
        __nv_bfloat16 hi[4], lo[4];
#pragma unroll
        for (int j = 0; j < 4; j++) split_bf16(av[j], hi[j], lo[j]);
        char* ph = smem + m * PAD + kk * 2;
        *(__nv_bfloat162*)(ph)     = __nv_bfloat162(hi[0], hi[1]);
        *(__nv_bfloat162*)(ph + 4) = __nv_bfloat162(hi[2], hi[3]);
        char* pl = ph + PLANE;
        *(__nv_bfloat162*)(pl)     = __nv_bfloat162(lo[0], lo[1]);
        *(__nv_bfloat162*)(pl + 4) = __nv_bfloat162(lo[2], lo[3]);

        int k = (tid >> 5) + 8 * l;
#pragma unroll
        for (int i = 0; i < 4; i++) {
            int n = (tid & 31) + 32 * i;
            __nv_bfloat16 bh, bl;
            split_bf16(pbv[l][i], bh, bl);
            *(__nv_bfloat16*)(smem + 2 * PLANE + n * PAD + k * 2) = bh;
            *(__nv_bfloat16*)(smem + 3 * PLANE + n * PAD + k * 2) = bl;
        }
    }
}

// fragment loads at PTX mma.m16n8k16 coordinates + 3-product split mma
__device__ __forceinline__ void compute_stage(const char* smem, int warp_m, int warp_n,
                                              int lane, float acc[4][4][4]) {
    const int g = lane >> 2;
    const int c = lane & 3;
    uint32_t bh[4][2], bl[4][2];
#pragma unroll
    for (int nt = 0; nt < 4; nt++) {
        const char* p = smem + 2 * PLANE + (uint32_t)(warp_n * 32 + nt * 8 + g) * PAD + c * 4;
        bh[nt][0] = *(const uint32_t*)(p);
        bh[nt][1] = *(const uint32_t*)(p + 16);
        const char* q = p + PLANE;
        bl[nt][0] = *(const uint32_t*)(q);
        bl[nt][1] = *(const uint32_t*)(q + 16);
    }
#pragma unroll
    for (int mt = 0; mt < 4; mt++) {
        const char* p = smem + (uint32_t)(warp_m * 64 + mt * 16 + g) * PAD + c * 4;
        uint32_t ah[4], al[4];
        ah[0] = *(const uint32_t*)(p);
        ah[1] = *(const uint32_t*)(p + 8 * PAD);
        ah[2] = *(const uint32_t*)(p + 16);
        ah[3] = *(const uint32_t*)(p + 8 * PAD + 16);
        const char* q = p + PLANE;
        al[0] = *(const uint32_t*)(q);
        al[1] = *(const uint32_t*)(q + 8 * PAD);
        al[2] = *(const uint32_t*)(q + 16);
        al[3] = *(const uint32_t*)(q + 8 * PAD + 16);
#pragma unroll
        for (int nt = 0; nt < 4; nt++) {
            mma16816(acc[mt][nt], ah, bh[nt]);
            mma16816(acc[mt][nt], ah, bl[nt]);
            mma16816(acc[mt][nt], al, bh[nt]);
        }
    }
}

// software-pipelined: regs hold chunk ch+2, smem double-buffers ch / ch+1.
// One __syncthreads per chunk.
template<bool GATHER>
__device__ __forceinline__ void mma_gemm(
    char* smem,
    const float* __restrict__ Abase, int lda, const int* __restrict__ toks,
    int m0, int cnt,
    const float* __restrict__ Bbase, int ldb, int n0, int K,
    float acc[4][4][4]) {
    const int lane = threadIdx.x & 31;
    const int wid  = threadIdx.x >> 5;
    const int warp_m = wid & 1, warp_n = wid >> 1;
#pragma unroll
    for (int i = 0; i < 4; i++)
#pragma unroll
        for (int j = 0; j < 4; j++)
#pragma unroll
            for (int q = 0; q < 4; q++) acc[i][j][q] = 0.0f;

    const int nchunks = K >> 4;
    float4 pa[2];
    float  pbv[2][4];
    // prologue: stage chunk 0 into buf0, load chunk 1 into regs
    fill_regs<GATHER>(pa, pbv, Abase, lda, toks, m0, cnt, Bbase, ldb, n0, 0);
    store_stage(smem, pa, pbv);
    if (nchunks > 1)
        fill_regs<GATHER>(pa, pbv, Abase, lda, toks, m0, cnt, Bbase, ldb, n0, 16);
    __syncthreads();
    for (int ch = 0; ch < nchunks; ch++) {
        if (ch + 1 < nchunks) {
            // store chunk ch+1 (its buffer's compute finished before last barrier)
            store_stage(smem + ((ch + 1) & 1) * STAGEB, pa, pbv);
            if (ch + 2 < nchunks)   // issue chunk ch+2 loads; hidden by compute below
                fill_regs<GATHER>(pa, pbv, Abase, lda, toks, m0, cnt, Bbase, ldb, n0,
                                  (ch + 2) << 4);
        }
        compute_stage(smem + (ch & 1) * STAGEB, warp_m, warp_n, lane, acc);
        __syncthreads();
    }
}

// ---------------- ffn1: h = gelu(Xg @ W1[e] + b1[e]) ----------------
__global__ __launch_bounds__(256, 2) void ffn1_kernel(const float* __restrict__ x,
                                                      const float* __restrict__ W1,
                                                      const float* __restrict__ b1) {
    __shared__ __align__(16) char smem[SMEMB];
    const int e   = blockIdx.z;
    const int cnt = g_cnt[e];
    const int m0  = blockIdx.y * 128;
    if (m0 >= cnt) return;
    const int n0  = blockIdx.x * 128;
    const int off = g_off[e];

    float acc[4][4][4];
    mma_gemm<true>(smem, x, DD, g_tok[e], m0, cnt,
                   W1 + (size_t)e * DD * HH, HH, n0, DD, acc);

    const int lane = threadIdx.x & 31;
    const int wid  = threadIdx.x >> 5;
    const int warp_m = wid & 1, warp_n = wid >> 1;
    const int g = lane >> 2, c2 = (lane & 3) << 1;
    const float* bias = b1 + (size_t)e * HH;
#pragma unroll
    for (int mt = 0; mt < 4; mt++) {
        int rl = m0 + warp_m * 64 + mt * 16 + g;
        int rh = rl + 8;
#pragma unroll
        for (int nt = 0; nt < 4; nt++) {
            int n = n0 + warp_n * 32 + nt * 8 + c2;
            float bn0 = bias[n], bn1 = bias[n + 1];
            if (rl < cnt) {
                float2 v;
                v.x = gelu_tanh(acc[mt][nt][0] + bn0);
                v.y = gelu_tanh(acc[mt][nt][1] + bn1);
                *(float2*)(g_h + (size_t)(off + rl) * HH + n) = v;
            }
            if (rh < cnt) {
                float2 v;
                v.x = gelu_tanh(acc[mt][nt][2] + bn0);
                v.y = gelu_tanh(acc[mt][nt][3] + bn1);
                *(float2*)(g_h + (size_t)(off + rh) * HH + n) = v;
            }
        }
    }
}

// ---------------- ffn2: out += w * (h @ W2[e] + b2[e]) ----------------
__global__ __launch_bounds__(256, 2) void ffn2_kernel(const float* __restrict__ W2,
                                                      const float* __restrict__ b2,
                                                      float* __restrict__ out) {
    __shared__ __align__(16) char smem[SMEMB];
    const int e   = blockIdx.z;
    const int cnt = g_cnt[e];
    const int m0  = blockIdx.y * 128;
    if (m0 >= cnt) return;
    const int n0  = blockIdx.x * 128;
    const int off = g_off[e];

    float acc[4][4][4];
    mma_gemm<false>(smem, g_h + (size_t)off * HH, HH, (const int*)0, m0, cnt,
                    W2 + (size_t)e * HH * DD, DD, n0, HH, acc);

    const int lane = threadIdx.x & 31;
    const int wid  = threadIdx.x >> 5;
    const int warp_m = wid & 1, warp_n = wid >> 1;
    const int g = lane >> 2, c2 = (lane & 3) << 1;
    const float* bias = b2 + (size_t)e * DD;
#pragma unroll
    for (int mt = 0; mt < 4; mt++) {
        int rl = m0 + warp_m * 64 + mt * 16 + g;
        int rh = rl + 8;
        int tl = 0, th = 0; float wl = 0.0f, wh = 0.0f;
        if (rl < cnt) { tl = g_tok[e][rl]; wl = g_wt[e][rl]; }
        if (rh < cnt) { th = g_tok[e][rh]; wh = g_wt[e][rh]; }
#pragma unroll
        for (int nt = 0; nt < 4; nt++) {
            int n = n0 + warp_n * 32 + nt * 8 + c2;
            float bn0 = bias[n], bn1 = bias[n + 1];
            if (rl < cnt) {
                float* o = out + (size_t)tl * DD + n;
                atomicAdd(&o[0], wl * (acc[mt][nt][0] + bn0));
                atomicAdd(&o[1], wl * (acc[mt][nt][1] + bn1));
            }
            if (rh < cnt) {
                float* o = out + (size_t)th * DD + n;
                atomicAdd(&o[0], wh * (acc[mt][nt][2] + bn0));
                atomicAdd(&o[1], wh * (acc[mt][nt][3] + bn1));
            }
        }
    }
}

// ---------------- launch ----------------
extern "C" void kernel_launch(void* const* d_in, const int* in_sizes, int n_in,
                              void* d_out, int out_size) {
    const float* x  = (const float*)d_in[0];   // [T, D]
    const float* Wg = (const float*)d_in[1];   // [D, E]
    const float* bg = (const float*)d_in[2];   // [E]
    const float* W1 = (const float*)d_in[3];   // [E, D, H]
    const float* b1 = (const float*)d_in[4];   // [E, H]
    const float* W2 = (const float*)d_in[5];   // [E, H, D]
    const float* b2 = (const float*)d_in[6];   // [E, D]
    float* out = (float*)d_out;

    int write_tail = (out_size >= TT * DD + 2 * TT) ? 1 : 0;

    zero_kernel<<<(TT * DD + 255) / 256, 256>>>(out);
    gate_kernel<<<TT / 8, 256>>>(x, Wg, bg, out, write_tail);
    scan_kernel<<<1, 32>>>();
    ffn1_kernel<<<dim3(HH / 128, TT / 128, EE), 256>>>(x, W1, b1);
    ffn2_kernel<<<dim3(DD / 128, TT / 128, EE), 256>>>(W2, b2, out);
}

// round 16
// speedup vs baseline: 2.0537x; 1.0236x over previous
#include <cuda_runtime.h>
#include <cuda_bf16.h>
#include <math.h>
#include <stdint.h>

#define TT 2048
#define DD 1024
#define HH 2048
#define EE 8
#define NA (2 * TT)

// ---- scratch (static device globals; no allocation allowed) ----
__device__ int   g_cnt[EE];
__device__ int   g_off[EE];
__device__ int   g_tok[EE][TT];
__device__ float g_wt[EE][TT];
__device__ float g_h[(size_t)NA * HH];   // 33.5 MB fp32 activations

__device__ __forceinline__ float gelu_tanh(float v) {
    const float c = 0.7978845608028654f;
    float u = c * (v + 0.044715f * v * v * v);
    return 0.5f * v * (1.0f + tanhf(u));
}
__device__ __forceinline__ void split_bf16(float v, __nv_bfloat16& h, __nv_bfloat16& l) {
    h = __float2bfloat16_rn(v);
    l = __float2bfloat16_rn(v - __bfloat162float(h));
}
__device__ __forceinline__ void mma16816(float* c, const uint32_t* a, const uint32_t* b) {
    asm volatile("mma.sync.aligned.m16n8k16.row.col.f32.bf16.bf16.f32 "
                 "{%0,%1,%2,%3}, {%4,%5,%6,%7}, {%8,%9}, {%0,%1,%2,%3};"
                 : "+f"(c[0]), "+f"(c[1]), "+f"(c[2]), "+f"(c[3])
                 : "r"(a[0]), "r"(a[1]), "r"(a[2]), "r"(a[3]), "r"(b[0]), "r"(b[1]));
}
__device__ __forceinline__ uint32_t smem_u32(const void* p) {
    uint32_t a;
    asm("{ .reg .u64 t; cvta.to.shared.u64 t, %1; cvt.u32.u64 %0, t; }" : "=r"(a) : "l"(p));
    return a;
}
__device__ __forceinline__ void ldsm4(uint32_t& r0, uint32_t& r1, uint32_t& r2, uint32_t& r3,
                                      uint32_t addr) {
    asm volatile("ldmatrix.sync.aligned.m8n8.x4.shared.b16 {%0,%1,%2,%3}, [%4];"
                 : "=r"(r0), "=r"(r1), "=r"(r2), "=r"(r3) : "r"(addr));
}

// ---------------- kernel 0: clear output + counters ----------------
__global__ void zero_kernel(float* out) {
    int i = blockIdx.x * blockDim.x + threadIdx.x;
    if (i < TT * DD) out[i] = 0.0f;
    if (i < EE) g_cnt[i] = 0;
}

// ---------------- kernel 1: gating (one warp / token) ----------------
__global__ void gate_kernel(const float* __restrict__ x,
                            const float* __restrict__ Wg,
                            const float* __restrict__ bg,
                            float* __restrict__ out, int write_tail) {
    int warp = (blockIdx.x * blockDim.x + threadIdx.x) >> 5;
    int lane = threadIdx.x & 31;
    if (warp >= TT) return;
    const float* xr = x + (size_t)warp * DD;
    float acc[EE];
#pragma unroll
    for (int e = 0; e < EE; e++) acc[e] = 0.0f;
    for (int i = lane; i < DD; i += 32) {
        float xv = xr[i];
        const float* wr = Wg + (size_t)i * EE;
#pragma unroll
        for (int e = 0; e < EE; e++) acc[e] += xv * wr[e];
    }
#pragma unroll
    for (int off = 16; off > 0; off >>= 1)
#pragma unroll
        for (int e = 0; e < EE; e++)
            acc[e] += __shfl_down_sync(0xffffffffu, acc[e], off);
    if (lane == 0) {
        float v[EE];
#pragma unroll
        for (int e = 0; e < EE; e++) v[e] = acc[e] + bg[e];
        int i0 = 0; float v0 = v[0];
#pragma unroll
        for (int e = 1; e < EE; e++) if (v[e] > v0) { v0 = v[e]; i0 = e; }
        int i1 = -1; float v1 = -3.4e38f;
#pragma unroll
        for (int e = 0; e < EE; e++)
            if (e != i0 && v[e] > v1) { v1 = v[e]; i1 = e; }
        float ex = __expf(v1 - v0);
        float inv = 1.0f / (1.0f + ex);
        int p0 = atomicAdd(&g_cnt[i0], 1);
        g_tok[i0][p0] = warp; g_wt[i0][p0] = inv;
        int p1 = atomicAdd(&g_cnt[i1], 1);
        g_tok[i1][p1] = warp; g_wt[i1][p1] = ex * inv;
        if (write_tail) {
            out[(size_t)TT * DD + warp * 2 + 0] = (float)i0;
            out[(size_t)TT * DD + warp * 2 + 1] = (float)i1;
        }
    }
}

__global__ void scan_kernel() {
    if (threadIdx.x == 0) {
        int run = 0;
#pragma unroll
        for (int e = 0; e < EE; e++) { g_off[e] = run; run += g_cnt[e]; }
    }
}

// ---------------- HMMA grouped GEMM with in-kernel bf16 split ----------------
// CTA 128x128, 256 threads, warps 2(m) x 4(n), warp tile 64x32, K-chunk 16.
// SMEM planes (bf16): Ah, Al (A [m][k]), Bh, Bl (B transposed to [n][k]).
// Row stride 48 B (16B-aligned for ldmatrix; 12-bank shift => conflict-free).
// Plane 6144 B; stage 24576 B; double-buffered = 49152 B static (48 KB limit).
#define PAD    48
#define PLANE  6144
#define STAGEB 24576
#define SMEMB  (2 * STAGEB)

// prefetch one fp32 K=16 chunk: A 2x float4; B 8 strided floats (lane-interleaved n)
template<bool GATHER>
__device__ __forceinline__ void fill_regs(
    float4 pa[2], float pbv[2][4],
    const float* __restrict__ Abase, int lda, const int* __restrict__ toks,
    int m0, int cnt,
    const float* __restrict__ Bbase, int ldb, int n0, int k0) {
    int tid = threadIdx.x;
#pragma unroll
    for (int l = 0; l < 2; l++) {
        int id = tid + l * 256;
        int m  = id >> 2;
        int kk = (id & 3) << 2;
        int r  = m0 + m;
        if (r < cnt) {
            int row = GATHER ? toks[r] : r;
            pa[l] = *(const float4*)(Abase + (size_t)row * lda + k0 + kk);
        } else {
            pa[l] = make_float4(0.f, 0.f, 0.f, 0.f);
        }
        int k = (tid >> 5) + 8 * l;
        const float* bp = Bbase + (size_t)(k0 + k) * ldb + n0 + (tid & 31);
#pragma unroll
        for (int i = 0; i < 4; i++) pbv[l][i] = bp[32 * i];
    }
}

// convert + store: A -> [m][k] planes, B -> transposed [n][k] planes
__device__ __forceinline__ void store_stage(char* smem, const float4 pa[2],
                                            const float pbv[2][4]) {
    int tid = threadIdx.x;
#pragma unroll
    for (int l = 0; l < 2; l++) {
        int id = tid + l * 256;
        int m  = id >> 2;
        int kk = (id & 3) << 2;
        float av[4] = {pa[l].x, pa[l].y, pa[l].z, pa[l].w};
        __nv_bfloat16 hi[4], lo[4];
#pragma unroll
        for (int j = 0; j < 4; j++) split_bf16(av[j], hi[j], lo[j]);
        char* ph = smem + m * PAD + kk * 2;
        *(__nv_bfloat162*)(ph)     = __nv_bfloat162(hi[0], hi[1]);
        *(__nv_bfloat162*)(ph + 4) = __nv_bfloat162(hi[2], hi[3]);
        char* pl = ph + PLANE;
        *(__nv_bfloat162*)(pl)     = __nv_bfloat162(lo[0], lo[1]);
        *(__nv_bfloat162*)(pl + 4) = __nv_bfloat162(lo[2], lo[3]);

        int k = (tid >> 5) + 8 * l;
#pragma unroll
        for (int i = 0; i < 4; i++) {
            int n = (tid & 31) + 32 * i;
            __nv_bfloat16 bh, bl;
            split_bf16(pbv[l][i], bh, bl);
            *(__nv_bfloat16*)(smem + 2 * PLANE + n * PAD + k * 2) = bh;
            *(__nv_bfloat16*)(smem + 3 * PLANE + n * PAD + k * 2) = bl;
        }
    }
}

// ldmatrix fragment loads (R6 lane formulas) + 3-product split mma
__device__ __forceinline__ void compute_stage(uint32_t base, int warp_m, int warp_n,
                                              int lane, float acc[4][4][4]) {
    // A: lanes 0-15 -> rows 0-15 of the 16x16 tile; lanes 16-31 -> k+8 halves
    const int laneA_row = lane & 15;
    const int laneA_cx  = (lane >> 4) * 16;
    // B: lanes 0-7 n0-7/k0-7, 8-15 n0-7/k8-15, 16-23 n8-15/k0-7, 24-31 n8-15/k8-15
    const int laneB_row = (lane & 7) + ((lane >> 4) << 3);
    const int laneB_cx  = ((lane >> 3) & 1) * 16;
    uint32_t aB = base + (uint32_t)(warp_m * 64 + laneA_row) * PAD + laneA_cx;
    uint32_t bB = base + 2 * PLANE + (uint32_t)(warp_n * 32 + laneB_row) * PAD + laneB_cx;

    uint32_t ah[4][4], al[4][4], bh[4][2], bl[4][2];
#pragma unroll
    for (int mt = 0; mt < 4; mt++) {
        ldsm4(ah[mt][0], ah[mt][1], ah[mt][2], ah[mt][3], aB + mt * 16 * PAD);
        ldsm4(al[mt][0], al[mt][1], al[mt][2], al[mt][3], aB + PLANE + mt * 16 * PAD);
    }
#pragma unroll
    for (int np = 0; np < 2; np++) {
        uint32_t r0, r1, r2, r3;
        ldsm4(r0, r1, r2, r3, bB + np * 16 * PAD);
        bh[np * 2][0] = r0; bh[np * 2][1] = r1;
        bh[np * 2 + 1][0] = r2; bh[np * 2 + 1][1] = r3;
        ldsm4(r0, r1, r2, r3, bB + PLANE + np * 16 * PAD);
        bl[np * 2][0] = r0; bl[np * 2][1] = r1;
        bl[np * 2 + 1][0] = r2; bl[np * 2 + 1][1] = r3;
    }
#pragma unroll
    for (int mt = 0; mt < 4; mt++)
#pragma unroll
        for (int nt = 0; nt < 4; nt++) {
            mma16816(acc[mt][nt], ah[mt], bh[nt]);
            mma16816(acc[mt][nt], ah[mt], bl[nt]);
            mma16816(acc[mt][nt], al[mt], bh[nt]);
        }
}

// software-pipelined: regs hold chunk ch+2, smem double-buffers ch / ch+1.
template<bool GATHER>
__device__ __forceinline__ void mma_gemm(
    char* smem, uint32_t sbase,
    const float* __restrict__ Abase, int lda, const int* __restrict__ toks,
    int m0, int cnt,
    const float* __restrict__ Bbase, int ldb, int n0, int K,
    float acc[4][4][4]) {
    const int lane = threadIdx.x & 31;
    const int wid  = threadIdx.x >> 5;
    const int warp_m = wid & 1, warp_n = wid >> 1;
#pragma unroll
    for (int i = 0; i < 4; i++)
#pragma unroll
        for (int j = 0; j < 4; j++)
#pragma unroll
            for (int q = 0; q < 4; q++) acc[i][j][q] = 0.0f;

    const int nchunks = K >> 4;
    float4 pa[2];
    float  pbv[2][4];
    fill_regs<GATHER>(pa, pbv, Abase, lda, toks, m0, cnt, Bbase, ldb, n0, 0);
    store_stage(smem, pa, pbv);
    if (nchunks > 1)
        fill_regs<GATHER>(pa, pbv, Abase, lda, toks, m0, cnt, Bbase, ldb, n0, 16);
    __syncthreads();
    for (int ch = 0; ch < nchunks; ch++) {
        if (ch + 1 < nchunks) {
            store_stage(smem + ((ch + 1) & 1) * STAGEB, pa, pbv);
            if (ch + 2 < nchunks)
                fill_regs<GATHER>(pa, pbv, Abase, lda, toks, m0, cnt, Bbase, ldb, n0,
                                  (ch + 2) << 4);
        }
        compute_stage(sbase + (ch & 1) * STAGEB, warp_m, warp_n, lane, acc);
        __syncthreads();
    }
}

// ---------------- ffn1: h = gelu(Xg @ W1[e] + b1[e]) ----------------
__global__ __launch_bounds__(256, 2) void ffn1_kernel(const float* __restrict__ x,
                                                      const float* __restrict__ W1,
                                                      const float* __restrict__ b1) {
    __shared__ __align__(16) char smem[SMEMB];
    const int e   = blockIdx.z;
    const int cnt = g_cnt[e];
    const int m0  = blockIdx.y * 128;
    if (m0 >= cnt) return;
    const int n0  = blockIdx.x * 128;
    const int off = g_off[e];

    float acc[4][4][4];
    mma_gemm<true>(smem, smem_u32(smem), x, DD, g_tok[e], m0, cnt,
                   W1 + (size_t)e * DD * HH, HH, n0, DD, acc);

    const int lane = threadIdx.x & 31;
    const int wid  = threadIdx.x >> 5;
    const int warp_m = wid & 1, warp_n = wid >> 1;
    const int g = lane >> 2, c2 = (lane & 3) << 1;
    const float* bias = b1 + (size_t)e * HH;
#pragma unroll
    for (int mt = 0; mt < 4; mt++) {
        int rl = m0 + warp_m * 64 + mt * 16 + g;
        int rh = rl + 8;
#pragma unroll
        for (int nt = 0; nt < 4; nt++) {
            int n = n0 + warp_n * 32 + nt * 8 + c2;
            float bn0 = bias[n], bn1 = bias[n + 1];
            if (rl < cnt) {
                float2 v;
                v.x = gelu_tanh(acc[mt][nt][0] + bn0);
                v.y = gelu_tanh(acc[mt][nt][1] + bn1);
                *(float2*)(g_h + (size_t)(off + rl) * HH + n) = v;
            }
            if (rh < cnt) {
                float2 v;
                v.x = gelu_tanh(acc[mt][nt][2] + bn0);
                v.y = gelu_tanh(acc[mt][nt][3] + bn1);
                *(float2*)(g_h + (size_t)(off + rh) * HH + n) = v;
            }
        }
    }
}

// ---------------- ffn2: out += w * (h @ W2[e] + b2[e]) ----------------
__global__ __launch_bounds__(256, 2) void ffn2_kernel(const float* __restrict__ W2,
                                                      const float* __restrict__ b2,
                                                      float* __restrict__ out) {
    __shared__ __align__(16) char smem[SMEMB];
    const int e   = blockIdx.z;
    const int cnt = g_cnt[e];
    const int m0  = blockIdx.y * 128;
    if (m0 >= cnt) return;
    const int n0  = blockIdx.x * 128;
    const int off = g_off[e];

    float acc[4][4][4];
    mma_gemm<false>(smem, smem_u32(smem), g_h + (size_t)off * HH, HH, (const int*)0,
                    m0, cnt, W2 + (size_t)e * HH * DD, DD, n0, HH, acc);

    const int lane = threadIdx.x & 31;
    const int wid  = threadIdx.x >> 5;
    const int warp_m = wid & 1, warp_n = wid >> 1;
    const int g = lane >> 2, c2 = (lane & 3) << 1;
    const float* bias = b2 + (size_t)e * DD;
#pragma unroll
    for (int mt = 0; mt < 4; mt++) {
        int rl = m0 + warp_m * 64 + mt * 16 + g;
        int rh = rl + 8;
        int tl = 0, th = 0; float wl = 0.0f, wh = 0.0f;
        if (rl < cnt) { tl = g_tok[e][rl]; wl = g_wt[e][rl]; }
        if (rh < cnt) { th = g_tok[e][rh]; wh = g_wt[e][rh]; }
#pragma unroll
        for (int nt = 0; nt < 4; nt++) {
            int n = n0 + warp_n * 32 + nt * 8 + c2;
            float bn0 = bias[n], bn1 = bias[n + 1];
            if (rl < cnt) {
                float* o = out + (size_t)tl * DD + n;
                atomicAdd(&o[0], wl * (acc[mt][nt][0] + bn0));
                atomicAdd(&o[1], wl * (acc[mt][nt][1] + bn1));
            }
            if (rh < cnt) {
                float* o = out + (size_t)th * DD + n;
                atomicAdd(&o[0], wh * (acc[mt][nt][2] + bn0));
                atomicAdd(&o[1], wh * (acc[mt][nt][3] + bn1));
            }
        }
    }
}

// ---------------- launch ----------------
extern "C" void kernel_launch(void* const* d_in, const int* in_sizes, int n_in,
                              void* d_out, int out_size) {
    const float* x  = (const float*)d_in[0];   // [T, D]
    const float* Wg = (const float*)d_in[1];   // [D, E]
    const float* bg = (const float*)d_in[2];   // [E]
    const float* W1 = (const float*)d_in[3];   // [E, D, H]
    const float* b1 = (const float*)d_in[4];   // [E, H]
    const float* W2 = (const float*)d_in[5];   // [E, H, D]
    const float* b2 = (const float*)d_in[6];   // [E, D]
    float* out = (float*)d_out;

    int write_tail = (out_size >= TT * DD + 2 * TT) ? 1 : 0;

    zero_kernel<<<(TT * DD + 255) / 256, 256>>>(out);
    gate_kernel<<<TT / 8, 256>>>(x, Wg, bg, out, write_tail);
    scan_kernel<<<1, 32>>>();
    ffn1_kernel<<<dim3(HH / 128, TT / 128, EE), 256>>>(x, W1, b1);
    ffn2_kernel<<<dim3(DD / 128, TT / 128, EE), 256>>>(W2, b2, out);
}